// round 14
// baseline (speedup 1.0000x reference)
#include <cuda_runtime.h>
#include <cuda_fp16.h>
#include <math.h>
#include <stdint.h>

#define SEQ    2048
#define HIDDEN 1024
#define MLP    4096
#define NH     16
#define HD     64

// ---------------- scratch (device globals: allocation-free) ----------------
__device__ __half g_h   [SEQ * HIDDEN];
__device__ __half g_qkvh[SEQ * 3 * HIDDEN];
__device__ __half g_att [SEQ * HIDDEN];
__device__ float  g_x1  [SEQ * HIDDEN];
__device__ __half g_h2  [SEQ * HIDDEN];
__device__ __half g_u   [SEQ * MLP];
__device__ __half g_wqkv[3 * HIDDEN * HIDDEN];
__device__ __half g_wo  [HIDDEN * HIDDEN];
__device__ __half g_upw [MLP * HIDDEN];
__device__ __half g_dnw [HIDDEN * MLP];

// ---------------- helpers ----------------------------------------------------
__device__ __forceinline__ uint32_t smem_u32(const void* p) {
    uint32_t a;
    asm("{ .reg .u64 t; cvta.to.shared.u64 t, %1; cvt.u32.u64 %0, t; }"
        : "=r"(a) : "l"(p));
    return a;
}
__device__ __forceinline__ void cp16(uint32_t saddr, const void* gptr) {
    asm volatile("cp.async.cg.shared.global [%0], [%1], 16;"
                 :: "r"(saddr), "l"(gptr));
}
__device__ __forceinline__ void cp_commit() {
    asm volatile("cp.async.commit_group;");
}
__device__ __forceinline__ void cp_wait1() {
    asm volatile("cp.async.wait_group 1;");
}
__device__ __forceinline__ void cp_wait0() {
    asm volatile("cp.async.wait_group 0;");
}
__device__ __forceinline__ void mma16816(float* c, const uint32_t* a, const uint32_t* b) {
    asm volatile(
        "mma.sync.aligned.m16n8k16.row.col.f32.f16.f16.f32 "
        "{%0,%1,%2,%3}, {%4,%5,%6,%7}, {%8,%9}, {%0,%1,%2,%3};"
        : "+f"(c[0]), "+f"(c[1]), "+f"(c[2]), "+f"(c[3])
        : "r"(a[0]), "r"(a[1]), "r"(a[2]), "r"(a[3]), "r"(b[0]), "r"(b[1]));
}
__device__ __forceinline__ void ldsm4(uint32_t* r, uint32_t a) {
    asm volatile("ldmatrix.sync.aligned.m8n8.x4.shared.b16 {%0,%1,%2,%3}, [%4];"
                 : "=r"(r[0]), "=r"(r[1]), "=r"(r[2]), "=r"(r[3]) : "r"(a));
}
__device__ __forceinline__ void ldsm4t(uint32_t* r, uint32_t a) {
    asm volatile("ldmatrix.sync.aligned.m8n8.x4.trans.shared.b16 {%0,%1,%2,%3}, [%4];"
                 : "=r"(r[0]), "=r"(r[1]), "=r"(r[2]), "=r"(r[3]) : "r"(a));
}
__device__ __forceinline__ uint32_t pack2h(float x, float y) {
    __half2 h = __floats2half2_rn(x, y);
    return *(uint32_t*)&h;
}
__device__ __forceinline__ float gelu_tanh(float v) {
    float c = 0.7978845608028654f * (v + 0.044715f * v * v * v);
    return 0.5f * v * (1.f + tanhf(c));
}
__device__ __forceinline__ void conv4(const float* __restrict__ src,
                                      __half* __restrict__ dst, int i) {
    float4 v = ((const float4*)src)[i];
    __half hh[4];
    hh[0] = __float2half_rn(v.x); hh[1] = __float2half_rn(v.y);
    hh[2] = __float2half_rn(v.z); hh[3] = __float2half_rn(v.w);
    *(uint2*)&dst[i * 4] = *(uint2*)hh;
}

// ---------------- prep: weight conversions (4 f4/thread) + LN0 ----------------
#define CV1 786432
#define CV2 262144
#define CV3 1048576
#define CV4 1048576
#define CB1 (CV1 / 1024)
#define CB2 (CV2 / 1024)
#define CB3 (CV3 / 1024)
#define CB4 (CV4 / 1024)
#define CONV_BLOCKS (CB1 + CB2 + CB3 + CB4)   // 3072

__global__ __launch_bounds__(256) void prep_kernel(
    const float* __restrict__ wqkv_w, const float* __restrict__ wo_w,
    const float* __restrict__ up_w,   const float* __restrict__ dn_w,
    __half* __restrict__ wqkv, __half* __restrict__ wo,
    __half* __restrict__ upw,  __half* __restrict__ dnw,
    const float* __restrict__ x, const float* __restrict__ n0w,
    const float* __restrict__ n0b, __half* __restrict__ h)
{
    int bid = blockIdx.x, tid = threadIdx.x;
    if (bid < CONV_BLOCKS) {
        const float* src;
        __half* dst;
        int b = bid;
        if (b < CB1)            { src = wqkv_w; dst = wqkv; }
        else if (b < CB1 + CB2) { src = wo_w;  dst = wo;  b -= CB1; }
        else if (b < CB1 + CB2 + CB3) { src = up_w; dst = upw; b -= CB1 + CB2; }
        else                    { src = dn_w;  dst = dnw; b -= CB1 + CB2 + CB3; }
        int base = b * 1024 + tid;
#pragma unroll
        for (int j = 0; j < 4; j++) conv4(src, dst, base + j * 256);
        return;
    }
    int row = bid - CONV_BLOCKS;
    float4 v = *(const float4*)&x[row * HIDDEN + tid * 4];
    float s  = v.x + v.y + v.z + v.w;
    float ss = v.x*v.x + v.y*v.y + v.z*v.z + v.w*v.w;
#pragma unroll
    for (int o = 16; o > 0; o >>= 1) {
        s  += __shfl_xor_sync(0xffffffffu, s,  o);
        ss += __shfl_xor_sync(0xffffffffu, ss, o);
    }
    __shared__ float2 red[8];
    int wid = tid >> 5, lane = tid & 31;
    if (lane == 0) red[wid] = make_float2(s, ss);
    __syncthreads();
    if (tid < 32) {
        float2 t = (tid < 8) ? red[tid] : make_float2(0.f, 0.f);
        s = t.x; ss = t.y;
#pragma unroll
        for (int o = 4; o > 0; o >>= 1) {
            s  += __shfl_xor_sync(0xffffffffu, s,  o);
            ss += __shfl_xor_sync(0xffffffffu, ss, o);
        }
        if (lane == 0) red[0] = make_float2(s, ss);
    }
    __syncthreads();
    float mean = red[0].x * (1.f / HIDDEN);
    float var  = red[0].y * (1.f / HIDDEN) - mean * mean;
    float rstd = rsqrtf(var + 1e-5f);
    float4 w4 = *(const float4*)&n0w[tid * 4];
    float4 b4 = *(const float4*)&n0b[tid * 4];
    __half hh[4];
    hh[0] = __float2half_rn((v.x - mean) * rstd * w4.x + b4.x);
    hh[1] = __float2half_rn((v.y - mean) * rstd * w4.y + b4.y);
    hh[2] = __float2half_rn((v.z - mean) * rstd * w4.z + b4.z);
    hh[3] = __float2half_rn((v.w - mean) * rstd * w4.w + b4.w);
    *(uint2*)&h[row * HIDDEN + tid * 4] = *(uint2*)hh;
}

// ---------------- LayerNorm (fp32 in, fp16 out) -------------------------------
__global__ __launch_bounds__(256) void ln_kernel(
    const float* __restrict__ x, const float* __restrict__ w,
    const float* __restrict__ b, __half* __restrict__ y)
{
    int row = blockIdx.x;
    int tid = threadIdx.x;
    float4 v = *(const float4*)&x[row * HIDDEN + tid * 4];
    float s  = v.x + v.y + v.z + v.w;
    float ss = v.x*v.x + v.y*v.y + v.z*v.z + v.w*v.w;
#pragma unroll
    for (int o = 16; o > 0; o >>= 1) {
        s  += __shfl_xor_sync(0xffffffffu, s,  o);
        ss += __shfl_xor_sync(0xffffffffu, ss, o);
    }
    __shared__ float2 red[8];
    int wid = tid >> 5, lane = tid & 31;
    if (lane == 0) red[wid] = make_float2(s, ss);
    __syncthreads();
    if (tid < 32) {
        float2 t = (tid < 8) ? red[tid] : make_float2(0.f, 0.f);
        s = t.x; ss = t.y;
#pragma unroll
        for (int o = 4; o > 0; o >>= 1) {
            s  += __shfl_xor_sync(0xffffffffu, s,  o);
            ss += __shfl_xor_sync(0xffffffffu, ss, o);
        }
        if (lane == 0) red[0] = make_float2(s, ss);
    }
    __syncthreads();
    float mean = red[0].x * (1.f / HIDDEN);
    float var  = red[0].y * (1.f / HIDDEN) - mean * mean;
    float rstd = rsqrtf(var + 1e-5f);
    float4 w4 = *(const float4*)&w[tid * 4];
    float4 b4 = *(const float4*)&b[tid * 4];
    __half h[4];
    h[0] = __float2half_rn((v.x - mean) * rstd * w4.x + b4.x);
    h[1] = __float2half_rn((v.y - mean) * rstd * w4.y + b4.y);
    h[2] = __float2half_rn((v.z - mean) * rstd * w4.z + b4.z);
    h[3] = __float2half_rn((v.w - mean) * rstd * w4.w + b4.w);
    *(uint2*)&y[row * HIDDEN + tid * 4] = *(uint2*)h;
}

// ---------------- HMMA GEMM (NT): C = A @ B^T + bias -------------------------
// Templated tile BMT x BNT, 8 warps, 3-stage cp.async, 1 barrier/k-step.
// EPI: 1 = +bias+res -> fp32; 2 = +bias,GELU -> fp16; 3 = +bias,RoPE -> fp16
#define BK 32
#define ROWB 80
#define NSTG 3

template <int EPI, int BMT, int BNT>
__global__ __launch_bounds__(256, ((BMT) == 64 ? 3 : 2)) void gemm_mma(
    const __half* __restrict__ A, const __half* __restrict__ B,
    const float* __restrict__ bias, const float* __restrict__ res,
    const float* __restrict__ cs, const float* __restrict__ sn,
    float* __restrict__ C, __half* __restrict__ Ch, int M, int N, int K)
{
    constexpr int MI = BMT / 32;
    constexpr int NI = BNT / 32;
    constexpr int STAGE = (BMT + BNT) * ROWB;
    constexpr int NLOAD = (BMT + BNT) * 4 / 256;

    extern __shared__ char smem[];
    uint32_t sb = smem_u32(smem);
    int tid = threadIdx.x, wid = tid >> 5, lane = tid & 31;
    int bm = blockIdx.y * BMT, bn = blockIdx.x * BNT;
    int wm = (wid >> 2) * (MI * 16), wn = (wid & 3) * (BNT / 4);
    int g = lane >> 2, t4 = lane & 3;

    float acc[MI][NI][4];
#pragma unroll
    for (int i = 0; i < MI; i++)
#pragma unroll
        for (int j = 0; j < NI; j++)
#pragma unroll
            for (int q = 0; q < 4; q++) acc[i][j][q] = 0.f;

    int arow = (lane & 7) + ((lane >> 3) & 1) * 8;
    int acol = ((lane >> 4) & 1) * 8;
    int brow = ((lane >> 4) & 1) * 8 + (lane & 7);
    int bcol = ((lane >> 3) & 1) * 8;

    int T = K / BK;
    auto load_stage = [&](int t) {
        uint32_t sbase = sb + (t % NSTG) * STAGE;
        int k0 = t * BK;
#pragma unroll
        for (int i = 0; i < NLOAD; i++) {
            int idx = tid + i * 256;
            int r = idx >> 2, c8 = (idx & 3) * 8;
            const __half* gp = (r < BMT)
                ? A + (size_t)(bm + r) * K + k0 + c8
                : B + (size_t)(bn + (r - BMT)) * K + k0 + c8;
            cp16(sbase + r * ROWB + c8 * 2, gp);
        }
        cp_commit();
    };

    load_stage(0);
    load_stage(1);

    for (int t = 0; t < T; t++) {
        if (t + 1 < T) cp_wait1(); else cp_wait0();
        __syncthreads();
        if (t + 2 < T) load_stage(t + 2);

        uint32_t base = sb + (t % NSTG) * STAGE;
#pragma unroll
        for (int ks = 0; ks < 2; ks++) {
            uint32_t a[MI][4], b[NI][2];
#pragma unroll
            for (int mi = 0; mi < MI; mi++)
                ldsm4(a[mi], base + (wm + mi * 16 + arow) * ROWB +
                             (ks * 16 + acol) * 2);
#pragma unroll
            for (int np = 0; np < NI / 2; np++) {
                uint32_t tmp[4];
                ldsm4(tmp, base + BMT * ROWB + (wn + np * 16 + brow) * ROWB +
                           (ks * 16 + bcol) * 2);
                b[2*np][0] = tmp[0]; b[2*np][1] = tmp[1];
                b[2*np+1][0] = tmp[2]; b[2*np+1][1] = tmp[3];
            }
#pragma unroll
            for (int mi = 0; mi < MI; mi++)
#pragma unroll
                for (int ni = 0; ni < NI; ni++)
                    mma16816(acc[mi][ni], a[mi], b[ni]);
        }
    }

#pragma unroll
    for (int mi = 0; mi < MI; mi++) {
#pragma unroll
        for (int ni = 0; ni < NI; ni++) {
            int n0 = bn + wn + ni * 8 + 2 * t4;
            float2 b2 = *(const float2*)&bias[n0];
            float v0 = acc[mi][ni][0] + b2.x;
            float v1 = acc[mi][ni][1] + b2.y;
            float v2 = acc[mi][ni][2] + b2.x;
            float v3 = acc[mi][ni][3] + b2.y;
            int m0 = bm + wm + mi * 16 + g;
            size_t off0 = (size_t)m0 * N + n0;
            size_t off1 = (size_t)(m0 + 8) * N + n0;
            if (EPI == 1) {
                float2 r0 = *(const float2*)&res[off0];
                float2 r1 = *(const float2*)&res[off1];
                v0 += r0.x; v1 += r0.y; v2 += r1.x; v3 += r1.y;
                *(float2*)&C[off0] = make_float2(v0, v1);
                *(float2*)&C[off1] = make_float2(v2, v3);
            }
            if (EPI == 2) {
                v0 = gelu_tanh(v0); v1 = gelu_tanh(v1);
                v2 = gelu_tanh(v2); v3 = gelu_tanh(v3);
                *(uint32_t*)&Ch[off0] = pack2h(v0, v1);
                *(uint32_t*)&Ch[off1] = pack2h(v2, v3);
            }
            if (EPI == 3) {
                if (n0 < 2 * HIDDEN) {
                    int p = (n0 & 63) >> 1;
                    float c0 = cs[m0 * 32 + p],       s0 = sn[m0 * 32 + p];
                    float c1 = cs[(m0 + 8) * 32 + p], s1 = sn[(m0 + 8) * 32 + p];
                    float r0 = v0 * c0 - v1 * s0, i0 = v0 * s0 + v1 * c0;
                    float r1 = v2 * c1 - v3 * s1, i1 = v2 * s1 + v3 * c1;
                    if (n0 < HIDDEN) {
                        r0 *= 0.125f; i0 *= 0.125f;
                        r1 *= 0.125f; i1 *= 0.125f;
                    }
                    v0 = r0; v1 = i0; v2 = r1; v3 = i1;
                }
                *(uint32_t*)&Ch[off0] = pack2h(v0, v1);
                *(uint32_t*)&Ch[off1] = pack2h(v2, v3);
            }
        }
    }
}

#define SMEM_T(BMT, BNT) (NSTG * ((BMT) + (BNT)) * ROWB)

// ---------------- Attention: HMMA flash, BQ=128 (8 warps), BKt=64 -------------
#define KROW 144

__global__ __launch_bounds__(256) void attn_mma(
    const __half* __restrict__ qkvh, const int* __restrict__ offs, int noffs,
    __half* __restrict__ o_out)
{
    __shared__ __align__(16) char sK[2][64 * KROW];
    __shared__ __align__(16) char sV[2][64 * KROW];
    __shared__ int segk[2][64];

    int head = blockIdx.x, qb = blockIdx.y;
    int tid  = threadIdx.x;
    int w = tid >> 5, lane = tid & 31;
    int t4 = lane & 3;
    int g = lane >> 2;
    int brow = ((lane >> 4) & 1) * 8 + (lane & 7);
    int bcol = ((lane >> 3) & 1) * 8;
    int vrow = (lane & 7) + ((lane >> 3) & 1) * 8;
    int vcol = ((lane >> 4) & 1) * 16;

    uint32_t qh[4][4];
    int qr0 = qb * 128 + w * 16 + g;
    {
        const __half* q0 = qkvh + (size_t)qr0 * 3072 + head * 64;
#pragma unroll
        for (int kk = 0; kk < 4; kk++) {
            int c0 = kk * 16 + 2 * t4;
            qh[kk][0] = *(const uint32_t*)(q0 + c0);
            qh[kk][1] = *(const uint32_t*)(q0 + 8 * 3072 + c0);
            qh[kk][2] = *(const uint32_t*)(q0 + c0 + 8);
            qh[kk][3] = *(const uint32_t*)(q0 + 8 * 3072 + c0 + 8);
        }
    }
    int segq0 = 0, segq8 = 0;
    for (int t = 0; t < noffs; t++) {
        if (offs[t] <= qr0)     segq0++;
        if (offs[t] <= qr0 + 8) segq8++;
    }
    segq0--; segq8--;

    auto load_tile = [&](int kt) {
        int buf = kt & 1;
        int row  = (tid >> 1) & 63;
        int half = tid & 1;
        int kv   = tid >> 7;
        const __half* src = qkvh + (size_t)(kt * 64 + row) * 3072 +
                            (kv ? 2048 : 1024) + head * 64 + half * 32;
        uint32_t dst = smem_u32(kv ? &sV[buf][row * KROW + half * 64]
                                   : &sK[buf][row * KROW + half * 64]);
#pragma unroll
        for (int i = 0; i < 4; i++) cp16(dst + i * 16, src + i * 8);
        cp_commit();
        if (tid < 64) {
            int kg = kt * 64 + tid;
            int c2 = 0;
            for (int t = 0; t < noffs; t++) if (offs[t] <= kg) c2++;
            segk[buf][tid] = c2 - 1;
        }
    };

    float o[8][4];
#pragma unroll
    for (int nt = 0; nt < 8; nt++)
#pragma unroll
        for (int q = 0; q < 4; q++) o[nt][q] = 0.f;
    float m0 = -1e30f, m8 = -1e30f, l0 = 0.f, l8 = 0.f;

    load_tile(0);

    for (int kt = 0; kt < SEQ / 64; kt++) {
        int buf = kt & 1;
        cp_wait0();
        __syncthreads();
        if (kt + 1 < SEQ / 64) load_tile(kt + 1);

        uint32_t aK = smem_u32(sK[buf]), aV = smem_u32(sV[buf]);

        float s[8][4];
#pragma unroll
        for (int nt = 0; nt < 8; nt++)
#pragma unroll
            for (int q = 0; q < 4; q++) s[nt][q] = 0.f;
#pragma unroll
        for (int kk = 0; kk < 4; kk++) {
#pragma unroll
            for (int ntp = 0; ntp < 4; ntp++) {
                uint32_t tmp[4];
                ldsm4(tmp, aK + (uint32_t)((ntp * 16 + brow) * KROW +
                                           (kk * 16 + bcol) * 2));
                uint32_t b0[2] = {tmp[0], tmp[1]};
                uint32_t b1[2] = {tmp[2], tmp[3]};
                mma16816(s[2*ntp],     qh[kk], b0);
                mma16816(s[2*ntp + 1], qh[kk], b1);
            }
        }
        float mt0 = -1e30f, mt8 = -1e30f;
#pragma unroll
        for (int nt = 0; nt < 8; nt++) {
            int sc0 = segk[buf][nt * 8 + 2 * t4];
            int sc1 = segk[buf][nt * 8 + 2 * t4 + 1];
            s[nt][0] += (segq0 == sc0) ? 1.f : 0.f;
            s[nt][1] += (segq0 == sc1) ? 1.f : 0.f;
            s[nt][2] += (segq8 == sc0) ? 1.f : 0.f;
            s[nt][3] += (segq8 == sc1) ? 1.f : 0.f;
            mt0 = fmaxf(mt0, fmaxf(s[nt][0], s[nt][1]));
            mt8 = fmaxf(mt8, fmaxf(s[nt][2], s[nt][3]));
        }
        mt0 = fmaxf(mt0, __shfl_xor_sync(0xffffffffu, mt0, 1));
        mt0 = fmaxf(mt0, __shfl_xor_sync(0xffffffffu, mt0, 2));
        mt8 = fmaxf(mt8, __shfl_xor_sync(0xffffffffu, mt8, 1));
        mt8 = fmaxf(mt8, __shfl_xor_sync(0xffffffffu, mt8, 2));
        float mn0 = fmaxf(m0, mt0), mn8 = fmaxf(m8, mt8);
        float corr0 = __expf(m0 - mn0), corr8 = __expf(m8 - mn8);
        m0 = mn0; m8 = mn8;
        float lp0 = 0.f, lp8 = 0.f;
#pragma unroll
        for (int nt = 0; nt < 8; nt++) {
            s[nt][0] = __expf(s[nt][0] - mn0);
            s[nt][1] = __expf(s[nt][1] - mn0);
            s[nt][2] = __expf(s[nt][2] - mn8);
            s[nt][3] = __expf(s[nt][3] - mn8);
            lp0 += s[nt][0] + s[nt][1];
            lp8 += s[nt][2] + s[nt][3];
        }
        lp0 += __shfl_xor_sync(0xffffffffu, lp0, 1);
        lp0 += __shfl_xor_sync(0xffffffffu, lp0, 2);
        lp8 += __shfl_xor_sync(0xffffffffu, lp8, 1);
        lp8 += __shfl_xor_sync(0xffffffffu, lp8, 2);
        l0 = l0 * corr0 + lp0;
        l8 = l8 * corr8 + lp8;
#pragma unroll
        for (int nt = 0; nt < 8; nt++) {
            o[nt][0] *= corr0; o[nt][1] *= corr0;
            o[nt][2] *= corr8; o[nt][3] *= corr8;
        }
#pragma unroll
        for (int kk = 0; kk < 4; kk++) {
            uint32_t pa[4];
            pa[0] = pack2h(s[2*kk][0],   s[2*kk][1]);
            pa[1] = pack2h(s[2*kk][2],   s[2*kk][3]);
            pa[2] = pack2h(s[2*kk+1][0], s[2*kk+1][1]);
            pa[3] = pack2h(s[2*kk+1][2], s[2*kk+1][3]);
#pragma unroll
            for (int ntp = 0; ntp < 4; ntp++) {
                uint32_t tmp[4];
                ldsm4t(tmp, aV + (uint32_t)((kk * 16 + vrow) * KROW +
                                            ntp * 32 + vcol));
                uint32_t v0[2] = {tmp[0], tmp[1]};
                uint32_t v1[2] = {tmp[2], tmp[3]};
                mma16816(o[2*ntp],     pa, v0);
                mma16816(o[2*ntp + 1], pa, v1);
            }
        }
        __syncthreads();
    }

    float inv0 = 1.f / l0, inv8 = 1.f / l8;
    size_t r0off = (size_t)qr0 * HIDDEN + head * 64;
    size_t r8off = r0off + 8 * HIDDEN;
#pragma unroll
    for (int nt = 0; nt < 8; nt++) {
        int col = nt * 8 + 2 * t4;
        *(uint32_t*)&o_out[r0off + col] = pack2h(o[nt][0] * inv0, o[nt][1] * inv0);
        *(uint32_t*)&o_out[r8off + col] = pack2h(o[nt][2] * inv8, o[nt][3] * inv8);
    }
}

// ---------------- launch ------------------------------------------------------
extern "C" void kernel_launch(void* const* d_in, const int* in_sizes, int n_in,
                              void* d_out, int out_size)
{
    const float* x        = (const float*)d_in[0];
    const float* rope_cos = (const float*)d_in[1];
    const float* rope_sin = (const float*)d_in[2];
    const float* norm0_w  = (const float*)d_in[3];
    const float* norm0_b  = (const float*)d_in[4];
    const float* norm1_w  = (const float*)d_in[5];
    const float* norm1_b  = (const float*)d_in[6];
    const float* wqkv_w   = (const float*)d_in[7];
    const float* wqkv_b   = (const float*)d_in[8];
    const float* wo_w     = (const float*)d_in[9];
    const float* wo_b     = (const float*)d_in[10];
    const float* up_w     = (const float*)d_in[11];
    const float* up_b     = (const float*)d_in[12];
    const float* down_w   = (const float*)d_in[13];
    const float* down_b   = (const float*)d_in[14];
    const int*   offs     = (const int*)d_in[15];
    int noffs = in_sizes[15];
    float* out = (float*)d_out;

    __half *h, *qkvh, *att, *h2, *u, *wqkv, *wo, *upw, *dnw;
    float *x1;
    cudaGetSymbolAddress((void**)&h,    g_h);
    cudaGetSymbolAddress((void**)&qkvh, g_qkvh);
    cudaGetSymbolAddress((void**)&att,  g_att);
    cudaGetSymbolAddress((void**)&x1,   g_x1);
    cudaGetSymbolAddress((void**)&h2,   g_h2);
    cudaGetSymbolAddress((void**)&u,    g_u);
    cudaGetSymbolAddress((void**)&wqkv, g_wqkv);
    cudaGetSymbolAddress((void**)&wo,   g_wo);
    cudaGetSymbolAddress((void**)&upw,  g_upw);
    cudaGetSymbolAddress((void**)&dnw,  g_dnw);

    cudaFuncSetAttribute((const void*)gemm_mma<3,128,128>, cudaFuncAttributeMaxDynamicSharedMemorySize, SMEM_T(128,128));
    cudaFuncSetAttribute((const void*)gemm_mma<2,128,128>, cudaFuncAttributeMaxDynamicSharedMemorySize, SMEM_T(128,128));
    cudaFuncSetAttribute((const void*)gemm_mma<1,64,128>,  cudaFuncAttributeMaxDynamicSharedMemorySize, SMEM_T(64,128));
    cudaFuncSetAttribute((const void*)gemm_mma<1,128,128>, cudaFuncAttributeMaxDynamicSharedMemorySize, SMEM_T(128,128));

    // 1. prep: all weight conversions (4 f4/thread) + LN0
    prep_kernel<<<CONV_BLOCKS + SEQ, 256>>>(
        wqkv_w, wo_w, up_w, down_w, wqkv, wo, upw, dnw,
        x, norm0_w, norm0_b, h);
    // 2. QKV GEMM + fused RoPE + q-scale -> qkvh (fp16)
    gemm_mma<3,128,128><<<dim3(3*HIDDEN/128, SEQ/128), 256, SMEM_T(128,128)>>>(
        h, wqkv, wqkv_b, nullptr, rope_cos, rope_sin,
        nullptr, qkvh, SEQ, 3*HIDDEN, HIDDEN);
    // 3. attention (BQ=128) -> att (fp16)
    attn_mma<<<dim3(NH, SEQ / 128), 256>>>(qkvh, offs, noffs, att);
    // 4. WO GEMM + residual -> x1 (fp32)  [short-K: 64x128, 256 CTAs]
    gemm_mma<1,64,128><<<dim3(HIDDEN/128, SEQ/64), 256, SMEM_T(64,128)>>>(
        att, wo, wo_b, x, nullptr, nullptr,
        x1, nullptr, SEQ, HIDDEN, HIDDEN);
    // 5. LN1 -> h2 (fp16)
    ln_kernel<<<SEQ, 256>>>(x1, norm1_w, norm1_b, h2);
    // 6. UP GEMM + GELU -> u (fp16)
    gemm_mma<2,128,128><<<dim3(MLP/128, SEQ/128), 256, SMEM_T(128,128)>>>(
        h2, upw, up_b, nullptr, nullptr, nullptr,
        nullptr, u, SEQ, MLP, HIDDEN);
    // 7. DOWN GEMM + residual -> out (fp32)  [long-K: 128x128, 128 CTAs]
    gemm_mma<1,128,128><<<dim3(HIDDEN/128, SEQ/128), 256, SMEM_T(128,128)>>>(
        u, dnw, down_b, x1, nullptr, nullptr,
        out, nullptr, SEQ, HIDDEN, MLP);
}

// round 15
// speedup vs baseline: 1.0065x; 1.0065x over previous
#include <cuda_runtime.h>
#include <cuda_fp16.h>
#include <math.h>
#include <stdint.h>

#define SEQ    2048
#define HIDDEN 1024
#define MLP    4096
#define NH     16
#define HD     64

// ---------------- scratch (device globals: allocation-free) ----------------
__device__ __half g_h   [SEQ * HIDDEN];
__device__ __half g_qkvh[SEQ * 3 * HIDDEN];
__device__ __half g_att [SEQ * HIDDEN];
__device__ float  g_x1  [SEQ * HIDDEN];
__device__ __half g_h2  [SEQ * HIDDEN];
__device__ __half g_u   [SEQ * MLP];
__device__ __half g_wqkv[3 * HIDDEN * HIDDEN];
__device__ __half g_wo  [HIDDEN * HIDDEN];
__device__ __half g_upw [MLP * HIDDEN];
__device__ __half g_dnw [HIDDEN * MLP];

// ---------------- helpers ----------------------------------------------------
__device__ __forceinline__ uint32_t smem_u32(const void* p) {
    uint32_t a;
    asm("{ .reg .u64 t; cvta.to.shared.u64 t, %1; cvt.u32.u64 %0, t; }"
        : "=r"(a) : "l"(p));
    return a;
}
__device__ __forceinline__ void cp16(uint32_t saddr, const void* gptr) {
    asm volatile("cp.async.cg.shared.global [%0], [%1], 16;"
                 :: "r"(saddr), "l"(gptr));
}
__device__ __forceinline__ void cp_commit() {
    asm volatile("cp.async.commit_group;");
}
__device__ __forceinline__ void cp_wait1() {
    asm volatile("cp.async.wait_group 1;");
}
__device__ __forceinline__ void cp_wait0() {
    asm volatile("cp.async.wait_group 0;");
}
__device__ __forceinline__ void mma16816(float* c, const uint32_t* a, const uint32_t* b) {
    asm volatile(
        "mma.sync.aligned.m16n8k16.row.col.f32.f16.f16.f32 "
        "{%0,%1,%2,%3}, {%4,%5,%6,%7}, {%8,%9}, {%0,%1,%2,%3};"
        : "+f"(c[0]), "+f"(c[1]), "+f"(c[2]), "+f"(c[3])
        : "r"(a[0]), "r"(a[1]), "r"(a[2]), "r"(a[3]), "r"(b[0]), "r"(b[1]));
}
__device__ __forceinline__ void ldsm4(uint32_t* r, uint32_t a) {
    asm volatile("ldmatrix.sync.aligned.m8n8.x4.shared.b16 {%0,%1,%2,%3}, [%4];"
                 : "=r"(r[0]), "=r"(r[1]), "=r"(r[2]), "=r"(r[3]) : "r"(a));
}
__device__ __forceinline__ void ldsm4t(uint32_t* r, uint32_t a) {
    asm volatile("ldmatrix.sync.aligned.m8n8.x4.trans.shared.b16 {%0,%1,%2,%3}, [%4];"
                 : "=r"(r[0]), "=r"(r[1]), "=r"(r[2]), "=r"(r[3]) : "r"(a));
}
__device__ __forceinline__ uint32_t pack2h(float x, float y) {
    __half2 h = __floats2half2_rn(x, y);
    return *(uint32_t*)&h;
}
__device__ __forceinline__ float gelu_tanh(float v) {
    float c = 0.7978845608028654f * (v + 0.044715f * v * v * v);
    return 0.5f * v * (1.f + tanhf(c));
}
__device__ __forceinline__ void conv4(const float* __restrict__ src,
                                      __half* __restrict__ dst, int i) {
    float4 v = ((const float4*)src)[i];
    __half hh[4];
    hh[0] = __float2half_rn(v.x); hh[1] = __float2half_rn(v.y);
    hh[2] = __float2half_rn(v.z); hh[3] = __float2half_rn(v.w);
    *(uint2*)&dst[i * 4] = *(uint2*)hh;
}

// ---------------- prep: weight conversions (4 f4/thread) + LN0 ----------------
#define CV1 786432
#define CV2 262144
#define CV3 1048576
#define CV4 1048576
#define CB1 (CV1 / 1024)
#define CB2 (CV2 / 1024)
#define CB3 (CV3 / 1024)
#define CB4 (CV4 / 1024)
#define CONV_BLOCKS (CB1 + CB2 + CB3 + CB4)   // 3072

__global__ __launch_bounds__(256) void prep_kernel(
    const float* __restrict__ wqkv_w, const float* __restrict__ wo_w,
    const float* __restrict__ up_w,   const float* __restrict__ dn_w,
    __half* __restrict__ wqkv, __half* __restrict__ wo,
    __half* __restrict__ upw,  __half* __restrict__ dnw,
    const float* __restrict__ x, const float* __restrict__ n0w,
    const float* __restrict__ n0b, __half* __restrict__ h)
{
    int bid = blockIdx.x, tid = threadIdx.x;
    if (bid < CONV_BLOCKS) {
        const float* src;
        __half* dst;
        int b = bid;
        if (b < CB1)            { src = wqkv_w; dst = wqkv; }
        else if (b < CB1 + CB2) { src = wo_w;  dst = wo;  b -= CB1; }
        else if (b < CB1 + CB2 + CB3) { src = up_w; dst = upw; b -= CB1 + CB2; }
        else                    { src = dn_w;  dst = dnw; b -= CB1 + CB2 + CB3; }
        int base = b * 1024 + tid;
#pragma unroll
        for (int j = 0; j < 4; j++) conv4(src, dst, base + j * 256);
        return;
    }
    int row = bid - CONV_BLOCKS;
    float4 v = *(const float4*)&x[row * HIDDEN + tid * 4];
    float s  = v.x + v.y + v.z + v.w;
    float ss = v.x*v.x + v.y*v.y + v.z*v.z + v.w*v.w;
#pragma unroll
    for (int o = 16; o > 0; o >>= 1) {
        s  += __shfl_xor_sync(0xffffffffu, s,  o);
        ss += __shfl_xor_sync(0xffffffffu, ss, o);
    }
    __shared__ float2 red[8];
    int wid = tid >> 5, lane = tid & 31;
    if (lane == 0) red[wid] = make_float2(s, ss);
    __syncthreads();
    if (tid < 32) {
        float2 t = (tid < 8) ? red[tid] : make_float2(0.f, 0.f);
        s = t.x; ss = t.y;
#pragma unroll
        for (int o = 4; o > 0; o >>= 1) {
            s  += __shfl_xor_sync(0xffffffffu, s,  o);
            ss += __shfl_xor_sync(0xffffffffu, ss, o);
        }
        if (lane == 0) red[0] = make_float2(s, ss);
    }
    __syncthreads();
    float mean = red[0].x * (1.f / HIDDEN);
    float var  = red[0].y * (1.f / HIDDEN) - mean * mean;
    float rstd = rsqrtf(var + 1e-5f);
    float4 w4 = *(const float4*)&n0w[tid * 4];
    float4 b4 = *(const float4*)&n0b[tid * 4];
    __half hh[4];
    hh[0] = __float2half_rn((v.x - mean) * rstd * w4.x + b4.x);
    hh[1] = __float2half_rn((v.y - mean) * rstd * w4.y + b4.y);
    hh[2] = __float2half_rn((v.z - mean) * rstd * w4.z + b4.z);
    hh[3] = __float2half_rn((v.w - mean) * rstd * w4.w + b4.w);
    *(uint2*)&h[row * HIDDEN + tid * 4] = *(uint2*)hh;
}

// ---------------- LayerNorm (fp32 in, fp16 out) -------------------------------
__global__ __launch_bounds__(256) void ln_kernel(
    const float* __restrict__ x, const float* __restrict__ w,
    const float* __restrict__ b, __half* __restrict__ y)
{
    int row = blockIdx.x;
    int tid = threadIdx.x;
    float4 v = *(const float4*)&x[row * HIDDEN + tid * 4];
    float s  = v.x + v.y + v.z + v.w;
    float ss = v.x*v.x + v.y*v.y + v.z*v.z + v.w*v.w;
#pragma unroll
    for (int o = 16; o > 0; o >>= 1) {
        s  += __shfl_xor_sync(0xffffffffu, s,  o);
        ss += __shfl_xor_sync(0xffffffffu, ss, o);
    }
    __shared__ float2 red[8];
    int wid = tid >> 5, lane = tid & 31;
    if (lane == 0) red[wid] = make_float2(s, ss);
    __syncthreads();
    if (tid < 32) {
        float2 t = (tid < 8) ? red[tid] : make_float2(0.f, 0.f);
        s = t.x; ss = t.y;
#pragma unroll
        for (int o = 4; o > 0; o >>= 1) {
            s  += __shfl_xor_sync(0xffffffffu, s,  o);
            ss += __shfl_xor_sync(0xffffffffu, ss, o);
        }
        if (lane == 0) red[0] = make_float2(s, ss);
    }
    __syncthreads();
    float mean = red[0].x * (1.f / HIDDEN);
    float var  = red[0].y * (1.f / HIDDEN) - mean * mean;
    float rstd = rsqrtf(var + 1e-5f);
    float4 w4 = *(const float4*)&w[tid * 4];
    float4 b4 = *(const float4*)&b[tid * 4];
    __half h[4];
    h[0] = __float2half_rn((v.x - mean) * rstd * w4.x + b4.x);
    h[1] = __float2half_rn((v.y - mean) * rstd * w4.y + b4.y);
    h[2] = __float2half_rn((v.z - mean) * rstd * w4.z + b4.z);
    h[3] = __float2half_rn((v.w - mean) * rstd * w4.w + b4.w);
    *(uint2*)&y[row * HIDDEN + tid * 4] = *(uint2*)h;
}

// ---------------- HMMA GEMM (NT): C = A @ B^T + bias -------------------------
// Templated tile BMT x BNT, 8 warps, 3-stage cp.async, 1 barrier/k-step.
// EPI: 1 = +bias+res -> fp32; 2 = +bias,GELU -> fp16; 3 = +bias,RoPE -> fp16
#define BK 32
#define ROWB 80
#define NSTG 3

template <int EPI, int BMT, int BNT>
__global__ __launch_bounds__(256, ((BMT) == 64 ? 3 : 2)) void gemm_mma(
    const __half* __restrict__ A, const __half* __restrict__ B,
    const float* __restrict__ bias, const float* __restrict__ res,
    const float* __restrict__ cs, const float* __restrict__ sn,
    float* __restrict__ C, __half* __restrict__ Ch, int M, int N, int K)
{
    constexpr int MI = BMT / 32;
    constexpr int NI = BNT / 32;
    constexpr int STAGE = (BMT + BNT) * ROWB;
    constexpr int NLOAD = (BMT + BNT) * 4 / 256;

    extern __shared__ char smem[];
    uint32_t sb = smem_u32(smem);
    int tid = threadIdx.x, wid = tid >> 5, lane = tid & 31;
    int bm = blockIdx.y * BMT, bn = blockIdx.x * BNT;
    int wm = (wid >> 2) * (MI * 16), wn = (wid & 3) * (BNT / 4);
    int g = lane >> 2, t4 = lane & 3;

    float acc[MI][NI][4];
#pragma unroll
    for (int i = 0; i < MI; i++)
#pragma unroll
        for (int j = 0; j < NI; j++)
#pragma unroll
            for (int q = 0; q < 4; q++) acc[i][j][q] = 0.f;

    int arow = (lane & 7) + ((lane >> 3) & 1) * 8;
    int acol = ((lane >> 4) & 1) * 8;
    int brow = ((lane >> 4) & 1) * 8 + (lane & 7);
    int bcol = ((lane >> 3) & 1) * 8;

    int T = K / BK;
    auto load_stage = [&](int t) {
        uint32_t sbase = sb + (t % NSTG) * STAGE;
        int k0 = t * BK;
#pragma unroll
        for (int i = 0; i < NLOAD; i++) {
            int idx = tid + i * 256;
            int r = idx >> 2, c8 = (idx & 3) * 8;
            const __half* gp = (r < BMT)
                ? A + (size_t)(bm + r) * K + k0 + c8
                : B + (size_t)(bn + (r - BMT)) * K + k0 + c8;
            cp16(sbase + r * ROWB + c8 * 2, gp);
        }
        cp_commit();
    };

    load_stage(0);
    load_stage(1);

    for (int t = 0; t < T; t++) {
        if (t + 1 < T) cp_wait1(); else cp_wait0();
        __syncthreads();
        if (t + 2 < T) load_stage(t + 2);

        uint32_t base = sb + (t % NSTG) * STAGE;
#pragma unroll
        for (int ks = 0; ks < 2; ks++) {
            uint32_t a[MI][4], b[NI][2];
#pragma unroll
            for (int mi = 0; mi < MI; mi++)
                ldsm4(a[mi], base + (wm + mi * 16 + arow) * ROWB +
                             (ks * 16 + acol) * 2);
#pragma unroll
            for (int np = 0; np < NI / 2; np++) {
                uint32_t tmp[4];
                ldsm4(tmp, base + BMT * ROWB + (wn + np * 16 + brow) * ROWB +
                           (ks * 16 + bcol) * 2);
                b[2*np][0] = tmp[0]; b[2*np][1] = tmp[1];
                b[2*np+1][0] = tmp[2]; b[2*np+1][1] = tmp[3];
            }
#pragma unroll
            for (int mi = 0; mi < MI; mi++)
#pragma unroll
                for (int ni = 0; ni < NI; ni++)
                    mma16816(acc[mi][ni], a[mi], b[ni]);
        }
    }

#pragma unroll
    for (int mi = 0; mi < MI; mi++) {
#pragma unroll
        for (int ni = 0; ni < NI; ni++) {
            int n0 = bn + wn + ni * 8 + 2 * t4;
            float2 b2 = *(const float2*)&bias[n0];
            float v0 = acc[mi][ni][0] + b2.x;
            float v1 = acc[mi][ni][1] + b2.y;
            float v2 = acc[mi][ni][2] + b2.x;
            float v3 = acc[mi][ni][3] + b2.y;
            int m0 = bm + wm + mi * 16 + g;
            size_t off0 = (size_t)m0 * N + n0;
            size_t off1 = (size_t)(m0 + 8) * N + n0;
            if (EPI == 1) {
                float2 r0 = *(const float2*)&res[off0];
                float2 r1 = *(const float2*)&res[off1];
                v0 += r0.x; v1 += r0.y; v2 += r1.x; v3 += r1.y;
                *(float2*)&C[off0] = make_float2(v0, v1);
                *(float2*)&C[off1] = make_float2(v2, v3);
            }
            if (EPI == 2) {
                v0 = gelu_tanh(v0); v1 = gelu_tanh(v1);
                v2 = gelu_tanh(v2); v3 = gelu_tanh(v3);
                *(uint32_t*)&Ch[off0] = pack2h(v0, v1);
                *(uint32_t*)&Ch[off1] = pack2h(v2, v3);
            }
            if (EPI == 3) {
                if (n0 < 2 * HIDDEN) {
                    int p = (n0 & 63) >> 1;
                    float c0 = cs[m0 * 32 + p],       s0 = sn[m0 * 32 + p];
                    float c1 = cs[(m0 + 8) * 32 + p], s1 = sn[(m0 + 8) * 32 + p];
                    float r0 = v0 * c0 - v1 * s0, i0 = v0 * s0 + v1 * c0;
                    float r1 = v2 * c1 - v3 * s1, i1 = v2 * s1 + v3 * c1;
                    if (n0 < HIDDEN) {
                        r0 *= 0.125f; i0 *= 0.125f;
                        r1 *= 0.125f; i1 *= 0.125f;
                    }
                    v0 = r0; v1 = i0; v2 = r1; v3 = i1;
                }
                *(uint32_t*)&Ch[off0] = pack2h(v0, v1);
                *(uint32_t*)&Ch[off1] = pack2h(v2, v3);
            }
        }
    }
}

#define SMEM_T(BMT, BNT) (NSTG * ((BMT) + (BNT)) * ROWB)

// ---------------- Attention: HMMA flash, BQ=128 (8 warps), BKt=64 -------------
#define KROW 144

__global__ __launch_bounds__(256) void attn_mma(
    const __half* __restrict__ qkvh, const int* __restrict__ offs, int noffs,
    __half* __restrict__ o_out)
{
    __shared__ __align__(16) char sK[2][64 * KROW];
    __shared__ __align__(16) char sV[2][64 * KROW];
    __shared__ int segk[2][64];

    int head = blockIdx.x, qb = blockIdx.y;
    int tid  = threadIdx.x;
    int w = tid >> 5, lane = tid & 31;
    int t4 = lane & 3;
    int g = lane >> 2;
    int brow = ((lane >> 4) & 1) * 8 + (lane & 7);
    int bcol = ((lane >> 3) & 1) * 8;
    int vrow = (lane & 7) + ((lane >> 3) & 1) * 8;
    int vcol = ((lane >> 4) & 1) * 16;

    uint32_t qh[4][4];
    int qr0 = qb * 128 + w * 16 + g;
    {
        const __half* q0 = qkvh + (size_t)qr0 * 3072 + head * 64;
#pragma unroll
        for (int kk = 0; kk < 4; kk++) {
            int c0 = kk * 16 + 2 * t4;
            qh[kk][0] = *(const uint32_t*)(q0 + c0);
            qh[kk][1] = *(const uint32_t*)(q0 + 8 * 3072 + c0);
            qh[kk][2] = *(const uint32_t*)(q0 + c0 + 8);
            qh[kk][3] = *(const uint32_t*)(q0 + 8 * 3072 + c0 + 8);
        }
    }
    int segq0 = 0, segq8 = 0;
    for (int t = 0; t < noffs; t++) {
        if (offs[t] <= qr0)     segq0++;
        if (offs[t] <= qr0 + 8) segq8++;
    }
    segq0--; segq8--;

    auto load_tile = [&](int kt) {
        int buf = kt & 1;
        int row  = (tid >> 1) & 63;
        int half = tid & 1;
        int kv   = tid >> 7;
        const __half* src = qkvh + (size_t)(kt * 64 + row) * 3072 +
                            (kv ? 2048 : 1024) + head * 64 + half * 32;
        uint32_t dst = smem_u32(kv ? &sV[buf][row * KROW + half * 64]
                                   : &sK[buf][row * KROW + half * 64]);
#pragma unroll
        for (int i = 0; i < 4; i++) cp16(dst + i * 16, src + i * 8);
        cp_commit();
        if (tid < 64) {
            int kg = kt * 64 + tid;
            int c2 = 0;
            for (int t = 0; t < noffs; t++) if (offs[t] <= kg) c2++;
            segk[buf][tid] = c2 - 1;
        }
    };

    float o[8][4];
#pragma unroll
    for (int nt = 0; nt < 8; nt++)
#pragma unroll
        for (int q = 0; q < 4; q++) o[nt][q] = 0.f;
    float m0 = -1e30f, m8 = -1e30f, l0 = 0.f, l8 = 0.f;

    load_tile(0);

    for (int kt = 0; kt < SEQ / 64; kt++) {
        int buf = kt & 1;
        cp_wait0();
        __syncthreads();
        if (kt + 1 < SEQ / 64) load_tile(kt + 1);

        uint32_t aK = smem_u32(sK[buf]), aV = smem_u32(sV[buf]);

        float s[8][4];
#pragma unroll
        for (int nt = 0; nt < 8; nt++)
#pragma unroll
            for (int q = 0; q < 4; q++) s[nt][q] = 0.f;
#pragma unroll
        for (int kk = 0; kk < 4; kk++) {
#pragma unroll
            for (int ntp = 0; ntp < 4; ntp++) {
                uint32_t tmp[4];
                ldsm4(tmp, aK + (uint32_t)((ntp * 16 + brow) * KROW +
                                           (kk * 16 + bcol) * 2));
                uint32_t b0[2] = {tmp[0], tmp[1]};
                uint32_t b1[2] = {tmp[2], tmp[3]};
                mma16816(s[2*ntp],     qh[kk], b0);
                mma16816(s[2*ntp + 1], qh[kk], b1);
            }
        }
        float mt0 = -1e30f, mt8 = -1e30f;
#pragma unroll
        for (int nt = 0; nt < 8; nt++) {
            int sc0 = segk[buf][nt * 8 + 2 * t4];
            int sc1 = segk[buf][nt * 8 + 2 * t4 + 1];
            s[nt][0] += (segq0 == sc0) ? 1.f : 0.f;
            s[nt][1] += (segq0 == sc1) ? 1.f : 0.f;
            s[nt][2] += (segq8 == sc0) ? 1.f : 0.f;
            s[nt][3] += (segq8 == sc1) ? 1.f : 0.f;
            mt0 = fmaxf(mt0, fmaxf(s[nt][0], s[nt][1]));
            mt8 = fmaxf(mt8, fmaxf(s[nt][2], s[nt][3]));
        }
        mt0 = fmaxf(mt0, __shfl_xor_sync(0xffffffffu, mt0, 1));
        mt0 = fmaxf(mt0, __shfl_xor_sync(0xffffffffu, mt0, 2));
        mt8 = fmaxf(mt8, __shfl_xor_sync(0xffffffffu, mt8, 1));
        mt8 = fmaxf(mt8, __shfl_xor_sync(0xffffffffu, mt8, 2));
        float mn0 = fmaxf(m0, mt0), mn8 = fmaxf(m8, mt8);
        float corr0 = __expf(m0 - mn0), corr8 = __expf(m8 - mn8);
        m0 = mn0; m8 = mn8;
        float lp0 = 0.f, lp8 = 0.f;
#pragma unroll
        for (int nt = 0; nt < 8; nt++) {
            s[nt][0] = __expf(s[nt][0] - mn0);
            s[nt][1] = __expf(s[nt][1] - mn0);
            s[nt][2] = __expf(s[nt][2] - mn8);
            s[nt][3] = __expf(s[nt][3] - mn8);
            lp0 += s[nt][0] + s[nt][1];
            lp8 += s[nt][2] + s[nt][3];
        }
        lp0 += __shfl_xor_sync(0xffffffffu, lp0, 1);
        lp0 += __shfl_xor_sync(0xffffffffu, lp0, 2);
        lp8 += __shfl_xor_sync(0xffffffffu, lp8, 1);
        lp8 += __shfl_xor_sync(0xffffffffu, lp8, 2);
        l0 = l0 * corr0 + lp0;
        l8 = l8 * corr8 + lp8;
#pragma unroll
        for (int nt = 0; nt < 8; nt++) {
            o[nt][0] *= corr0; o[nt][1] *= corr0;
            o[nt][2] *= corr8; o[nt][3] *= corr8;
        }
#pragma unroll
        for (int kk = 0; kk < 4; kk++) {
            uint32_t pa[4];
            pa[0] = pack2h(s[2*kk][0],   s[2*kk][1]);
            pa[1] = pack2h(s[2*kk][2],   s[2*kk][3]);
            pa[2] = pack2h(s[2*kk+1][0], s[2*kk+1][1]);
            pa[3] = pack2h(s[2*kk+1][2], s[2*kk+1][3]);
#pragma unroll
            for (int ntp = 0; ntp < 4; ntp++) {
                uint32_t tmp[4];
                ldsm4t(tmp, aV + (uint32_t)((kk * 16 + vrow) * KROW +
                                            ntp * 32 + vcol));
                uint32_t v0[2] = {tmp[0], tmp[1]};
                uint32_t v1[2] = {tmp[2], tmp[3]};
                mma16816(o[2*ntp],     pa, v0);
                mma16816(o[2*ntp + 1], pa, v1);
            }
        }
        __syncthreads();
    }

    float inv0 = 1.f / l0, inv8 = 1.f / l8;
    size_t r0off = (size_t)qr0 * HIDDEN + head * 64;
    size_t r8off = r0off + 8 * HIDDEN;
#pragma unroll
    for (int nt = 0; nt < 8; nt++) {
        int col = nt * 8 + 2 * t4;
        *(uint32_t*)&o_out[r0off + col] = pack2h(o[nt][0] * inv0, o[nt][1] * inv0);
        *(uint32_t*)&o_out[r8off + col] = pack2h(o[nt][2] * inv8, o[nt][3] * inv8);
    }
}

// ---------------- launch ------------------------------------------------------
extern "C" void kernel_launch(void* const* d_in, const int* in_sizes, int n_in,
                              void* d_out, int out_size)
{
    const float* x        = (const float*)d_in[0];
    const float* rope_cos = (const float*)d_in[1];
    const float* rope_sin = (const float*)d_in[2];
    const float* norm0_w  = (const float*)d_in[3];
    const float* norm0_b  = (const float*)d_in[4];
    const float* norm1_w  = (const float*)d_in[5];
    const float* norm1_b  = (const float*)d_in[6];
    const float* wqkv_w   = (const float*)d_in[7];
    const float* wqkv_b   = (const float*)d_in[8];
    const float* wo_w     = (const float*)d_in[9];
    const float* wo_b     = (const float*)d_in[10];
    const float* up_w     = (const float*)d_in[11];
    const float* up_b     = (const float*)d_in[12];
    const float* down_w   = (const float*)d_in[13];
    const float* down_b   = (const float*)d_in[14];
    const int*   offs     = (const int*)d_in[15];
    int noffs = in_sizes[15];
    float* out = (float*)d_out;

    __half *h, *qkvh, *att, *h2, *u, *wqkv, *wo, *upw, *dnw;
    float *x1;
    cudaGetSymbolAddress((void**)&h,    g_h);
    cudaGetSymbolAddress((void**)&qkvh, g_qkvh);
    cudaGetSymbolAddress((void**)&att,  g_att);
    cudaGetSymbolAddress((void**)&x1,   g_x1);
    cudaGetSymbolAddress((void**)&h2,   g_h2);
    cudaGetSymbolAddress((void**)&u,    g_u);
    cudaGetSymbolAddress((void**)&wqkv, g_wqkv);
    cudaGetSymbolAddress((void**)&wo,   g_wo);
    cudaGetSymbolAddress((void**)&upw,  g_upw);
    cudaGetSymbolAddress((void**)&dnw,  g_dnw);

    cudaFuncSetAttribute((const void*)gemm_mma<3,64,128>, cudaFuncAttributeMaxDynamicSharedMemorySize, SMEM_T(64,128));
    cudaFuncSetAttribute((const void*)gemm_mma<2,64,128>, cudaFuncAttributeMaxDynamicSharedMemorySize, SMEM_T(64,128));
    cudaFuncSetAttribute((const void*)gemm_mma<1,64,128>, cudaFuncAttributeMaxDynamicSharedMemorySize, SMEM_T(64,128));

    // 1. prep: all weight conversions (4 f4/thread) + LN0
    prep_kernel<<<CONV_BLOCKS + SEQ, 256>>>(
        wqkv_w, wo_w, up_w, down_w, wqkv, wo, upw, dnw,
        x, norm0_w, norm0_b, h);
    // 2. QKV GEMM + fused RoPE + q-scale -> qkvh (fp16)  [64x128: 768 CTAs]
    gemm_mma<3,64,128><<<dim3(3*HIDDEN/128, SEQ/64), 256, SMEM_T(64,128)>>>(
        h, wqkv, wqkv_b, nullptr, rope_cos, rope_sin,
        nullptr, qkvh, SEQ, 3*HIDDEN, HIDDEN);
    // 3. attention (BQ=128) -> att (fp16)
    attn_mma<<<dim3(NH, SEQ / 128), 256>>>(qkvh, offs, noffs, att);
    // 4. WO GEMM + residual -> x1 (fp32)  [64x128: 256 CTAs]
    gemm_mma<1,64,128><<<dim3(HIDDEN/128, SEQ/64), 256, SMEM_T(64,128)>>>(
        att, wo, wo_b, x, nullptr, nullptr,
        x1, nullptr, SEQ, HIDDEN, HIDDEN);
    // 5. LN1 -> h2 (fp16)
    ln_kernel<<<SEQ, 256>>>(x1, norm1_w, norm1_b, h2);
    // 6. UP GEMM + GELU -> u (fp16)  [64x128: 1024 CTAs]
    gemm_mma<2,64,128><<<dim3(MLP/128, SEQ/64), 256, SMEM_T(64,128)>>>(
        h2, upw, up_b, nullptr, nullptr, nullptr,
        nullptr, u, SEQ, MLP, HIDDEN);
    // 7. DOWN GEMM + residual -> out (fp32)  [64x128: 256 CTAs]
    gemm_mma<1,64,128><<<dim3(HIDDEN/128, SEQ/64), 256, SMEM_T(64,128)>>>(
        u, dnw, down_b, x1, nullptr, nullptr,
        out, nullptr, SEQ, HIDDEN, MLP);
}

// round 16
// speedup vs baseline: 1.0305x; 1.0239x over previous
#include <cuda_runtime.h>
#include <cuda_fp16.h>
#include <math.h>
#include <stdint.h>

#define SEQ    2048
#define HIDDEN 1024
#define MLP    4096
#define NH     16
#define HD     64

// ---------------- scratch (device globals: allocation-free) ----------------
__device__ __half g_h   [SEQ * HIDDEN];
__device__ __half g_qkvh[SEQ * 3 * HIDDEN];
__device__ __half g_att [SEQ * HIDDEN];
__device__ float  g_x1  [SEQ * HIDDEN];
__device__ __half g_h2  [SEQ * HIDDEN];
__device__ __half g_u   [SEQ * MLP];
__device__ __half g_wqkv[3 * HIDDEN * HIDDEN];
__device__ __half g_wo  [HIDDEN * HIDDEN];
__device__ __half g_upw [MLP * HIDDEN];
__device__ __half g_dnw [HIDDEN * MLP];

// ---------------- helpers ----------------------------------------------------
__device__ __forceinline__ uint32_t smem_u32(const void* p) {
    uint32_t a;
    asm("{ .reg .u64 t; cvta.to.shared.u64 t, %1; cvt.u32.u64 %0, t; }"
        : "=r"(a) : "l"(p));
    return a;
}
__device__ __forceinline__ void gdc_wait() {
    asm volatile("griddepcontrol.wait;" ::: "memory");
}
__device__ __forceinline__ void gdc_launch() {
    asm volatile("griddepcontrol.launch_dependents;" ::: "memory");
}
__device__ __forceinline__ void cp16(uint32_t saddr, const void* gptr) {
    asm volatile("cp.async.cg.shared.global [%0], [%1], 16;"
                 :: "r"(saddr), "l"(gptr));
}
__device__ __forceinline__ void cp_commit() {
    asm volatile("cp.async.commit_group;");
}
__device__ __forceinline__ void cp_wait1() {
    asm volatile("cp.async.wait_group 1;");
}
__device__ __forceinline__ void cp_wait0() {
    asm volatile("cp.async.wait_group 0;");
}
__device__ __forceinline__ void mma16816(float* c, const uint32_t* a, const uint32_t* b) {
    asm volatile(
        "mma.sync.aligned.m16n8k16.row.col.f32.f16.f16.f32 "
        "{%0,%1,%2,%3}, {%4,%5,%6,%7}, {%8,%9}, {%0,%1,%2,%3};"
        : "+f"(c[0]), "+f"(c[1]), "+f"(c[2]), "+f"(c[3])
        : "r"(a[0]), "r"(a[1]), "r"(a[2]), "r"(a[3]), "r"(b[0]), "r"(b[1]));
}
__device__ __forceinline__ void ldsm4(uint32_t* r, uint32_t a) {
    asm volatile("ldmatrix.sync.aligned.m8n8.x4.shared.b16 {%0,%1,%2,%3}, [%4];"
                 : "=r"(r[0]), "=r"(r[1]), "=r"(r[2]), "=r"(r[3]) : "r"(a));
}
__device__ __forceinline__ void ldsm4t(uint32_t* r, uint32_t a) {
    asm volatile("ldmatrix.sync.aligned.m8n8.x4.trans.shared.b16 {%0,%1,%2,%3}, [%4];"
                 : "=r"(r[0]), "=r"(r[1]), "=r"(r[2]), "=r"(r[3]) : "r"(a));
}
__device__ __forceinline__ uint32_t pack2h(float x, float y) {
    __half2 h = __floats2half2_rn(x, y);
    return *(uint32_t*)&h;
}
__device__ __forceinline__ float gelu_tanh(float v) {
    float c = 0.7978845608028654f * (v + 0.044715f * v * v * v);
    return 0.5f * v * (1.f + tanhf(c));
}
__device__ __forceinline__ void conv4(const float* __restrict__ src,
                                      __half* __restrict__ dst, int i) {
    float4 v = ((const float4*)src)[i];
    __half hh[4];
    hh[0] = __float2half_rn(v.x); hh[1] = __float2half_rn(v.y);
    hh[2] = __float2half_rn(v.z); hh[3] = __float2half_rn(v.w);
    *(uint2*)&dst[i * 4] = *(uint2*)hh;
}

// ---------------- prep: weight conversions (4 f4/thread) + LN0 ----------------
#define CV1 786432
#define CV2 262144
#define CV3 1048576
#define CV4 1048576
#define CB1 (CV1 / 1024)
#define CB2 (CV2 / 1024)
#define CB3 (CV3 / 1024)
#define CB4 (CV4 / 1024)
#define CONV_BLOCKS (CB1 + CB2 + CB3 + CB4)   // 3072

__global__ __launch_bounds__(256) void prep_kernel(
    const float* __restrict__ wqkv_w, const float* __restrict__ wo_w,
    const float* __restrict__ up_w,   const float* __restrict__ dn_w,
    __half* __restrict__ wqkv, __half* __restrict__ wo,
    __half* __restrict__ upw,  __half* __restrict__ dnw,
    const float* __restrict__ x, const float* __restrict__ n0w,
    const float* __restrict__ n0b, __half* __restrict__ h)
{
    int bid = blockIdx.x, tid = threadIdx.x;
    if (bid < CONV_BLOCKS) {
        const float* src;
        __half* dst;
        int b = bid;
        if (b < CB1)            { src = wqkv_w; dst = wqkv; }
        else if (b < CB1 + CB2) { src = wo_w;  dst = wo;  b -= CB1; }
        else if (b < CB1 + CB2 + CB3) { src = up_w; dst = upw; b -= CB1 + CB2; }
        else                    { src = dn_w;  dst = dnw; b -= CB1 + CB2 + CB3; }
        int base = b * 1024 + tid;
#pragma unroll
        for (int j = 0; j < 4; j++) conv4(src, dst, base + j * 256);
        gdc_launch();
        return;
    }
    int row = bid - CONV_BLOCKS;
    float4 v = *(const float4*)&x[row * HIDDEN + tid * 4];
    float s  = v.x + v.y + v.z + v.w;
    float ss = v.x*v.x + v.y*v.y + v.z*v.z + v.w*v.w;
#pragma unroll
    for (int o = 16; o > 0; o >>= 1) {
        s  += __shfl_xor_sync(0xffffffffu, s,  o);
        ss += __shfl_xor_sync(0xffffffffu, ss, o);
    }
    __shared__ float2 red[8];
    int wid = tid >> 5, lane = tid & 31;
    if (lane == 0) red[wid] = make_float2(s, ss);
    __syncthreads();
    if (tid < 32) {
        float2 t = (tid < 8) ? red[tid] : make_float2(0.f, 0.f);
        s = t.x; ss = t.y;
#pragma unroll
        for (int o = 4; o > 0; o >>= 1) {
            s  += __shfl_xor_sync(0xffffffffu, s,  o);
            ss += __shfl_xor_sync(0xffffffffu, ss, o);
        }
        if (lane == 0) red[0] = make_float2(s, ss);
    }
    __syncthreads();
    float mean = red[0].x * (1.f / HIDDEN);
    float var  = red[0].y * (1.f / HIDDEN) - mean * mean;
    float rstd = rsqrtf(var + 1e-5f);
    float4 w4 = *(const float4*)&n0w[tid * 4];
    float4 b4 = *(const float4*)&n0b[tid * 4];
    __half hh[4];
    hh[0] = __float2half_rn((v.x - mean) * rstd * w4.x + b4.x);
    hh[1] = __float2half_rn((v.y - mean) * rstd * w4.y + b4.y);
    hh[2] = __float2half_rn((v.z - mean) * rstd * w4.z + b4.z);
    hh[3] = __float2half_rn((v.w - mean) * rstd * w4.w + b4.w);
    *(uint2*)&h[row * HIDDEN + tid * 4] = *(uint2*)hh;
    gdc_launch();
}

// ---------------- LayerNorm (fp32 in, fp16 out) -------------------------------
__global__ __launch_bounds__(256) void ln_kernel(
    const float* __restrict__ x, const float* __restrict__ w,
    const float* __restrict__ b, __half* __restrict__ y)
{
    int row = blockIdx.x;
    int tid = threadIdx.x;
    gdc_wait();
    float4 v = *(const float4*)&x[row * HIDDEN + tid * 4];
    float s  = v.x + v.y + v.z + v.w;
    float ss = v.x*v.x + v.y*v.y + v.z*v.z + v.w*v.w;
#pragma unroll
    for (int o = 16; o > 0; o >>= 1) {
        s  += __shfl_xor_sync(0xffffffffu, s,  o);
        ss += __shfl_xor_sync(0xffffffffu, ss, o);
    }
    __shared__ float2 red[8];
    int wid = tid >> 5, lane = tid & 31;
    if (lane == 0) red[wid] = make_float2(s, ss);
    __syncthreads();
    if (tid < 32) {
        float2 t = (tid < 8) ? red[tid] : make_float2(0.f, 0.f);
        s = t.x; ss = t.y;
#pragma unroll
        for (int o = 4; o > 0; o >>= 1) {
            s  += __shfl_xor_sync(0xffffffffu, s,  o);
            ss += __shfl_xor_sync(0xffffffffu, ss, o);
        }
        if (lane == 0) red[0] = make_float2(s, ss);
    }
    __syncthreads();
    float mean = red[0].x * (1.f / HIDDEN);
    float var  = red[0].y * (1.f / HIDDEN) - mean * mean;
    float rstd = rsqrtf(var + 1e-5f);
    float4 w4 = *(const float4*)&w[tid * 4];
    float4 b4 = *(const float4*)&b[tid * 4];
    __half h[4];
    h[0] = __float2half_rn((v.x - mean) * rstd * w4.x + b4.x);
    h[1] = __float2half_rn((v.y - mean) * rstd * w4.y + b4.y);
    h[2] = __float2half_rn((v.z - mean) * rstd * w4.z + b4.z);
    h[3] = __float2half_rn((v.w - mean) * rstd * w4.w + b4.w);
    *(uint2*)&y[row * HIDDEN + tid * 4] = *(uint2*)h;
    gdc_launch();
}

// ---------------- HMMA GEMM (NT): C = A @ B^T + bias -------------------------
// Templated tile BMT x BNT, 8 warps, 3-stage cp.async, 1 barrier/k-step.
// EPI: 1 = +bias+res -> fp32; 2 = +bias,GELU -> fp16; 3 = +bias,RoPE -> fp16
#define BK 32
#define ROWB 80
#define NSTG 3

template <int EPI, int BMT, int BNT>
__global__ __launch_bounds__(256, ((BMT) == 64 ? 3 : 2)) void gemm_mma(
    const __half* __restrict__ A, const __half* __restrict__ B,
    const float* __restrict__ bias, const float* __restrict__ res,
    const float* __restrict__ cs, const float* __restrict__ sn,
    float* __restrict__ C, __half* __restrict__ Ch, int M, int N, int K)
{
    constexpr int MI = BMT / 32;
    constexpr int NI = BNT / 32;
    constexpr int STAGE = (BMT + BNT) * ROWB;
    constexpr int NLOAD = (BMT + BNT) * 4 / 256;

    extern __shared__ char smem[];
    uint32_t sb = smem_u32(smem);
    int tid = threadIdx.x, wid = tid >> 5, lane = tid & 31;
    int bm = blockIdx.y * BMT, bn = blockIdx.x * BNT;
    int wm = (wid >> 2) * (MI * 16), wn = (wid & 3) * (BNT / 4);
    int g = lane >> 2, t4 = lane & 3;

    float acc[MI][NI][4];
#pragma unroll
    for (int i = 0; i < MI; i++)
#pragma unroll
        for (int j = 0; j < NI; j++)
#pragma unroll
            for (int q = 0; q < 4; q++) acc[i][j][q] = 0.f;

    int arow = (lane & 7) + ((lane >> 3) & 1) * 8;
    int acol = ((lane >> 4) & 1) * 8;
    int brow = ((lane >> 4) & 1) * 8 + (lane & 7);
    int bcol = ((lane >> 3) & 1) * 8;

    int T = K / BK;
    auto load_stage = [&](int t) {
        uint32_t sbase = sb + (t % NSTG) * STAGE;
        int k0 = t * BK;
#pragma unroll
        for (int i = 0; i < NLOAD; i++) {
            int idx = tid + i * 256;
            int r = idx >> 2, c8 = (idx & 3) * 8;
            const __half* gp = (r < BMT)
                ? A + (size_t)(bm + r) * K + k0 + c8
                : B + (size_t)(bn + (r - BMT)) * K + k0 + c8;
            cp16(sbase + r * ROWB + c8 * 2, gp);
        }
        cp_commit();
    };

    gdc_wait();
    load_stage(0);
    load_stage(1);

    for (int t = 0; t < T; t++) {
        if (t + 1 < T) cp_wait1(); else cp_wait0();
        __syncthreads();
        if (t + 2 < T) load_stage(t + 2);

        uint32_t base = sb + (t % NSTG) * STAGE;
#pragma unroll
        for (int ks = 0; ks < 2; ks++) {
            uint32_t a[MI][4], b[NI][2];
#pragma unroll
            for (int mi = 0; mi < MI; mi++)
                ldsm4(a[mi], base + (wm + mi * 16 + arow) * ROWB +
                             (ks * 16 + acol) * 2);
#pragma unroll
            for (int np = 0; np < NI / 2; np++) {
                uint32_t tmp[4];
                ldsm4(tmp, base + BMT * ROWB + (wn + np * 16 + brow) * ROWB +
                           (ks * 16 + bcol) * 2);
                b[2*np][0] = tmp[0]; b[2*np][1] = tmp[1];
                b[2*np+1][0] = tmp[2]; b[2*np+1][1] = tmp[3];
            }
#pragma unroll
            for (int mi = 0; mi < MI; mi++)
#pragma unroll
                for (int ni = 0; ni < NI; ni++)
                    mma16816(acc[mi][ni], a[mi], b[ni]);
        }
    }

#pragma unroll
    for (int mi = 0; mi < MI; mi++) {
#pragma unroll
        for (int ni = 0; ni < NI; ni++) {
            int n0 = bn + wn + ni * 8 + 2 * t4;
            float2 b2 = *(const float2*)&bias[n0];
            float v0 = acc[mi][ni][0] + b2.x;
            float v1 = acc[mi][ni][1] + b2.y;
            float v2 = acc[mi][ni][2] + b2.x;
            float v3 = acc[mi][ni][3] + b2.y;
            int m0 = bm + wm + mi * 16 + g;
            size_t off0 = (size_t)m0 * N + n0;
            size_t off1 = (size_t)(m0 + 8) * N + n0;
            if (EPI == 1) {
                float2 r0 = *(const float2*)&res[off0];
                float2 r1 = *(const float2*)&res[off1];
                v0 += r0.x; v1 += r0.y; v2 += r1.x; v3 += r1.y;
                *(float2*)&C[off0] = make_float2(v0, v1);
                *(float2*)&C[off1] = make_float2(v2, v3);
            }
            if (EPI == 2) {
                v0 = gelu_tanh(v0); v1 = gelu_tanh(v1);
                v2 = gelu_tanh(v2); v3 = gelu_tanh(v3);
                *(uint32_t*)&Ch[off0] = pack2h(v0, v1);
                *(uint32_t*)&Ch[off1] = pack2h(v2, v3);
            }
            if (EPI == 3) {
                if (n0 < 2 * HIDDEN) {
                    int p = (n0 & 63) >> 1;
                    float c0 = cs[m0 * 32 + p],       s0 = sn[m0 * 32 + p];
                    float c1 = cs[(m0 + 8) * 32 + p], s1 = sn[(m0 + 8) * 32 + p];
                    float r0 = v0 * c0 - v1 * s0, i0 = v0 * s0 + v1 * c0;
                    float r1 = v2 * c1 - v3 * s1, i1 = v2 * s1 + v3 * c1;
                    if (n0 < HIDDEN) {
                        r0 *= 0.125f; i0 *= 0.125f;
                        r1 *= 0.125f; i1 *= 0.125f;
                    }
                    v0 = r0; v1 = i0; v2 = r1; v3 = i1;
                }
                *(uint32_t*)&Ch[off0] = pack2h(v0, v1);
                *(uint32_t*)&Ch[off1] = pack2h(v2, v3);
            }
        }
    }
    gdc_launch();
}

#define SMEM_T(BMT, BNT) (NSTG * ((BMT) + (BNT)) * ROWB)

// ---------------- Attention: HMMA flash, BQ=128 (8 warps), BKt=64 -------------
#define KROW 144

__global__ __launch_bounds__(256) void attn_mma(
    const __half* __restrict__ qkvh, const int* __restrict__ offs, int noffs,
    __half* __restrict__ o_out)
{
    __shared__ __align__(16) char sK[2][64 * KROW];
    __shared__ __align__(16) char sV[2][64 * KROW];
    __shared__ int segk[2][64];

    int head = blockIdx.x, qb = blockIdx.y;
    int tid  = threadIdx.x;
    int w = tid >> 5, lane = tid & 31;
    int t4 = lane & 3;
    int g = lane >> 2;
    int brow = ((lane >> 4) & 1) * 8 + (lane & 7);
    int bcol = ((lane >> 3) & 1) * 8;
    int vrow = (lane & 7) + ((lane >> 3) & 1) * 8;
    int vcol = ((lane >> 4) & 1) * 16;

    gdc_wait();

    uint32_t qh[4][4];
    int qr0 = qb * 128 + w * 16 + g;
    {
        const __half* q0 = qkvh + (size_t)qr0 * 3072 + head * 64;
#pragma unroll
        for (int kk = 0; kk < 4; kk++) {
            int c0 = kk * 16 + 2 * t4;
            qh[kk][0] = *(const uint32_t*)(q0 + c0);
            qh[kk][1] = *(const uint32_t*)(q0 + 8 * 3072 + c0);
            qh[kk][2] = *(const uint32_t*)(q0 + c0 + 8);
            qh[kk][3] = *(const uint32_t*)(q0 + 8 * 3072 + c0 + 8);
        }
    }
    int segq0 = 0, segq8 = 0;
    for (int t = 0; t < noffs; t++) {
        if (offs[t] <= qr0)     segq0++;
        if (offs[t] <= qr0 + 8) segq8++;
    }
    segq0--; segq8--;

    auto load_tile = [&](int kt) {
        int buf = kt & 1;
        int row  = (tid >> 1) & 63;
        int half = tid & 1;
        int kv   = tid >> 7;
        const __half* src = qkvh + (size_t)(kt * 64 + row) * 3072 +
                            (kv ? 2048 : 1024) + head * 64 + half * 32;
        uint32_t dst = smem_u32(kv ? &sV[buf][row * KROW + half * 64]
                                   : &sK[buf][row * KROW + half * 64]);
#pragma unroll
        for (int i = 0; i < 4; i++) cp16(dst + i * 16, src + i * 8);
        cp_commit();
        if (tid < 64) {
            int kg = kt * 64 + tid;
            int c2 = 0;
            for (int t = 0; t < noffs; t++) if (offs[t] <= kg) c2++;
            segk[buf][tid] = c2 - 1;
        }
    };

    float o[8][4];
#pragma unroll
    for (int nt = 0; nt < 8; nt++)
#pragma unroll
        for (int q = 0; q < 4; q++) o[nt][q] = 0.f;
    float m0 = -1e30f, m8 = -1e30f, l0 = 0.f, l8 = 0.f;

    load_tile(0);

    for (int kt = 0; kt < SEQ / 64; kt++) {
        int buf = kt & 1;
        cp_wait0();
        __syncthreads();
        if (kt + 1 < SEQ / 64) load_tile(kt + 1);

        uint32_t aK = smem_u32(sK[buf]), aV = smem_u32(sV[buf]);

        float s[8][4];
#pragma unroll
        for (int nt = 0; nt < 8; nt++)
#pragma unroll
            for (int q = 0; q < 4; q++) s[nt][q] = 0.f;
#pragma unroll
        for (int kk = 0; kk < 4; kk++) {
#pragma unroll
            for (int ntp = 0; ntp < 4; ntp++) {
                uint32_t tmp[4];
                ldsm4(tmp, aK + (uint32_t)((ntp * 16 + brow) * KROW +
                                           (kk * 16 + bcol) * 2));
                uint32_t b0[2] = {tmp[0], tmp[1]};
                uint32_t b1[2] = {tmp[2], tmp[3]};
                mma16816(s[2*ntp],     qh[kk], b0);
                mma16816(s[2*ntp + 1], qh[kk], b1);
            }
        }
        float mt0 = -1e30f, mt8 = -1e30f;
#pragma unroll
        for (int nt = 0; nt < 8; nt++) {
            int sc0 = segk[buf][nt * 8 + 2 * t4];
            int sc1 = segk[buf][nt * 8 + 2 * t4 + 1];
            s[nt][0] += (segq0 == sc0) ? 1.f : 0.f;
            s[nt][1] += (segq0 == sc1) ? 1.f : 0.f;
            s[nt][2] += (segq8 == sc0) ? 1.f : 0.f;
            s[nt][3] += (segq8 == sc1) ? 1.f : 0.f;
            mt0 = fmaxf(mt0, fmaxf(s[nt][0], s[nt][1]));
            mt8 = fmaxf(mt8, fmaxf(s[nt][2], s[nt][3]));
        }
        mt0 = fmaxf(mt0, __shfl_xor_sync(0xffffffffu, mt0, 1));
        mt0 = fmaxf(mt0, __shfl_xor_sync(0xffffffffu, mt0, 2));
        mt8 = fmaxf(mt8, __shfl_xor_sync(0xffffffffu, mt8, 1));
        mt8 = fmaxf(mt8, __shfl_xor_sync(0xffffffffu, mt8, 2));
        float mn0 = fmaxf(m0, mt0), mn8 = fmaxf(m8, mt8);
        float corr0 = __expf(m0 - mn0), corr8 = __expf(m8 - mn8);
        m0 = mn0; m8 = mn8;
        float lp0 = 0.f, lp8 = 0.f;
#pragma unroll
        for (int nt = 0; nt < 8; nt++) {
            s[nt][0] = __expf(s[nt][0] - mn0);
            s[nt][1] = __expf(s[nt][1] - mn0);
            s[nt][2] = __expf(s[nt][2] - mn8);
            s[nt][3] = __expf(s[nt][3] - mn8);
            lp0 += s[nt][0] + s[nt][1];
            lp8 += s[nt][2] + s[nt][3];
        }
        lp0 += __shfl_xor_sync(0xffffffffu, lp0, 1);
        lp0 += __shfl_xor_sync(0xffffffffu, lp0, 2);
        lp8 += __shfl_xor_sync(0xffffffffu, lp8, 1);
        lp8 += __shfl_xor_sync(0xffffffffu, lp8, 2);
        l0 = l0 * corr0 + lp0;
        l8 = l8 * corr8 + lp8;
#pragma unroll
        for (int nt = 0; nt < 8; nt++) {
            o[nt][0] *= corr0; o[nt][1] *= corr0;
            o[nt][2] *= corr8; o[nt][3] *= corr8;
        }
#pragma unroll
        for (int kk = 0; kk < 4; kk++) {
            uint32_t pa[4];
            pa[0] = pack2h(s[2*kk][0],   s[2*kk][1]);
            pa[1] = pack2h(s[2*kk][2],   s[2*kk][3]);
            pa[2] = pack2h(s[2*kk+1][0], s[2*kk+1][1]);
            pa[3] = pack2h(s[2*kk+1][2], s[2*kk+1][3]);
#pragma unroll
            for (int ntp = 0; ntp < 4; ntp++) {
                uint32_t tmp[4];
                ldsm4t(tmp, aV + (uint32_t)((kk * 16 + vrow) * KROW +
                                            ntp * 32 + vcol));
                uint32_t v0[2] = {tmp[0], tmp[1]};
                uint32_t v1[2] = {tmp[2], tmp[3]};
                mma16816(o[2*ntp],     pa, v0);
                mma16816(o[2*ntp + 1], pa, v1);
            }
        }
        __syncthreads();
    }

    float inv0 = 1.f / l0, inv8 = 1.f / l8;
    size_t r0off = (size_t)qr0 * HIDDEN + head * 64;
    size_t r8off = r0off + 8 * HIDDEN;
#pragma unroll
    for (int nt = 0; nt < 8; nt++) {
        int col = nt * 8 + 2 * t4;
        *(uint32_t*)&o_out[r0off + col] = pack2h(o[nt][0] * inv0, o[nt][1] * inv0);
        *(uint32_t*)&o_out[r8off + col] = pack2h(o[nt][2] * inv8, o[nt][3] * inv8);
    }
    gdc_launch();
}

// ---------------- PDL launch helper -------------------------------------------
template <typename F, typename... Args>
static void launch_pdl(F* func, dim3 grid, dim3 block, size_t smem, Args... args) {
    cudaLaunchConfig_t cfg = {};
    cfg.gridDim = grid;
    cfg.blockDim = block;
    cfg.dynamicSmemBytes = smem;
    cfg.stream = 0;
    cudaLaunchAttribute attr[1];
    attr[0].id = cudaLaunchAttributeProgrammaticStreamSerialization;
    attr[0].val.programmaticStreamSerializationAllowed = 1;
    cfg.attrs = attr;
    cfg.numAttrs = 1;
    cudaLaunchKernelEx(&cfg, func, args...);
}

// ---------------- launch ------------------------------------------------------
extern "C" void kernel_launch(void* const* d_in, const int* in_sizes, int n_in,
                              void* d_out, int out_size)
{
    const float* x        = (const float*)d_in[0];
    const float* rope_cos = (const float*)d_in[1];
    const float* rope_sin = (const float*)d_in[2];
    const float* norm0_w  = (const float*)d_in[3];
    const float* norm0_b  = (const float*)d_in[4];
    const float* norm1_w  = (const float*)d_in[5];
    const float* norm1_b  = (const float*)d_in[6];
    const float* wqkv_w   = (const float*)d_in[7];
    const float* wqkv_b   = (const float*)d_in[8];
    const float* wo_w     = (const float*)d_in[9];
    const float* wo_b     = (const float*)d_in[10];
    const float* up_w     = (const float*)d_in[11];
    const float* up_b     = (const float*)d_in[12];
    const float* down_w   = (const float*)d_in[13];
    const float* down_b   = (const float*)d_in[14];
    const int*   offs     = (const int*)d_in[15];
    int noffs = in_sizes[15];
    float* out = (float*)d_out;

    __half *h, *qkvh, *att, *h2, *u, *wqkv, *wo, *upw, *dnw;
    float *x1;
    cudaGetSymbolAddress((void**)&h,    g_h);
    cudaGetSymbolAddress((void**)&qkvh, g_qkvh);
    cudaGetSymbolAddress((void**)&att,  g_att);
    cudaGetSymbolAddress((void**)&x1,   g_x1);
    cudaGetSymbolAddress((void**)&h2,   g_h2);
    cudaGetSymbolAddress((void**)&u,    g_u);
    cudaGetSymbolAddress((void**)&wqkv, g_wqkv);
    cudaGetSymbolAddress((void**)&wo,   g_wo);
    cudaGetSymbolAddress((void**)&upw,  g_upw);
    cudaGetSymbolAddress((void**)&dnw,  g_dnw);

    cudaFuncSetAttribute((const void*)gemm_mma<3,128,128>, cudaFuncAttributeMaxDynamicSharedMemorySize, SMEM_T(128,128));
    cudaFuncSetAttribute((const void*)gemm_mma<2,128,128>, cudaFuncAttributeMaxDynamicSharedMemorySize, SMEM_T(128,128));
    cudaFuncSetAttribute((const void*)gemm_mma<1,64,128>,  cudaFuncAttributeMaxDynamicSharedMemorySize, SMEM_T(64,128));

    // 1. prep: all weight conversions (4 f4/thread) + LN0
    prep_kernel<<<CONV_BLOCKS + SEQ, 256>>>(
        wqkv_w, wo_w, up_w, down_w, wqkv, wo, upw, dnw,
        x, norm0_w, norm0_b, h);
    // 2. QKV GEMM + fused RoPE + q-scale -> qkvh (fp16)  [128x128, PDL]
    launch_pdl(gemm_mma<3,128,128>, dim3(3*HIDDEN/128, SEQ/128), dim3(256),
               (size_t)SMEM_T(128,128),
               (const __half*)h, (const __half*)wqkv, wqkv_b, (const float*)nullptr,
               rope_cos, rope_sin, (float*)nullptr, (__half*)qkvh,
               (int)SEQ, (int)(3*HIDDEN), (int)HIDDEN);
    // 3. attention (BQ=128) -> att (fp16)  [PDL]
    launch_pdl(attn_mma, dim3(NH, SEQ / 128), dim3(256), (size_t)0,
               (const __half*)qkvh, offs, noffs, (__half*)att);
    // 4. WO GEMM + residual -> x1 (fp32)  [64x128, PDL]
    launch_pdl(gemm_mma<1,64,128>, dim3(HIDDEN/128, SEQ/64), dim3(256),
               (size_t)SMEM_T(64,128),
               (const __half*)att, (const __half*)wo, wo_b, x,
               (const float*)nullptr, (const float*)nullptr,
               (float*)x1, (__half*)nullptr,
               (int)SEQ, (int)HIDDEN, (int)HIDDEN);
    // 5. LN1 -> h2 (fp16)  [PDL]
    launch_pdl(ln_kernel, dim3(SEQ), dim3(256), (size_t)0,
               (const float*)x1, norm1_w, norm1_b, (__half*)h2);
    // 6. UP GEMM + GELU -> u (fp16)  [128x128, PDL]
    launch_pdl(gemm_mma<2,128,128>, dim3(MLP/128, SEQ/128), dim3(256),
               (size_t)SMEM_T(128,128),
               (const __half*)h2, (const __half*)upw, up_b, (const float*)nullptr,
               (const float*)nullptr, (const float*)nullptr,
               (float*)nullptr, (__half*)u,
               (int)SEQ, (int)MLP, (int)HIDDEN);
    // 7. DOWN GEMM + residual -> out (fp32)  [64x128, PDL]
    launch_pdl(gemm_mma<1,64,128>, dim3(HIDDEN/128, SEQ/64), dim3(256),
               (size_t)SMEM_T(64,128),
               (const __half*)u, (const __half*)dnw, down_b, (const float*)x1,
               (const float*)nullptr, (const float*)nullptr,
               (float*)out, (__half*)nullptr,
               (int)SEQ, (int)HIDDEN, (int)MLP);
}